// round 13
// baseline (speedup 1.0000x reference)
#include <cuda_runtime.h>
#include <cstddef>
#include <cstdint>

// ---------------- compile-time Gaussian weights (win=11, sigma=1.5) ----------
__host__ __device__ __forceinline__ constexpr float gw(int t) {
    return (t == 0  || t == 10) ? 0.00102848f
         : (t == 1  || t == 9 ) ? 0.00759876f
         : (t == 2  || t == 8 ) ? 0.03600078f
         : (t == 3  || t == 7 ) ? 0.10936057f
         : (t == 4  || t == 6 ) ? 0.21300557f
         :                        0.26601165f;   // t == 5
}

// ---------------- packed f32x2 helpers (sm_100+) ----------------
__device__ __forceinline__ uint64_t bcast2(float w) {
    uint64_t r; asm("mov.b64 %0, {%1, %1};" : "=l"(r) : "f"(w)); return r;
}
__device__ __forceinline__ uint64_t pk2(float x, float y) {
    uint64_t r; asm("mov.b64 %0, {%1, %2};" : "=l"(r) : "f"(x), "f"(y)); return r;
}
__device__ __forceinline__ float2 unpk(uint64_t v) {
    float2 p; asm("mov.b64 {%0, %1}, %2;" : "=f"(p.x), "=f"(p.y) : "l"(v)); return p;
}
__device__ __forceinline__ void fma2(uint64_t& d, uint64_t a, uint64_t b) {
    asm("fma.rn.f32x2 %0, %1, %2, %0;" : "+l"(d) : "l"(a), "l"(b));
}
__device__ __forceinline__ uint64_t mul2(uint64_t a, uint64_t b) {
    uint64_t d; asm("mul.rn.f32x2 %0, %1, %2;" : "=l"(d) : "l"(a), "l"(b)); return d;
}

// ---------------- cp.async helpers ----------------
__device__ __forceinline__ void cp_async16(uint32_t dst_smem, const void* src) {
    asm volatile("cp.async.cg.shared.global [%0], [%1], 16;"
                 :: "r"(dst_smem), "l"(src));
}
__device__ __forceinline__ void cp_commit() {
    asm volatile("cp.async.commit_group;" ::: "memory");
}
__device__ __forceinline__ void cp_wait0() {
    asm volatile("cp.async.wait_group 0;" ::: "memory");
}

#define TILE_W 32
#define TILE_H 64
#define IN_W   42          // TILE_W + 10
#define IN_H   74          // TILE_H + 10
#define NTHREADS 256

#define IMG_W 512
#define IMG_H 512
#define OUT_W 502
#define OUT_H 502
#define NCH   3

#define XP_STRIDE 44       // x/y planes: 16B-aligned rows, step-12 mod 32 -> CF
#define HS4_STRIDE 132     // 4 fields interleaved (float4 per col), 16B-aligned rows
#define HS1_STRIDE 33      // xy-blur scalar plane, odd stride (scalar access only!)

#define NCHUNK (IN_H * 11) // 814 cp.async 16B chunks per plane per channel

static constexpr float C1v = 6.5025f;    // (0.01*255)^2
static constexpr float C2v = 58.5225f;   // (0.03*255)^2

// smem floats: 2*74*44 + 74*132 + 74*33 = 18722 -> 74888 B -> 3 blocks/SM
#define SMEM_FLOATS (2 * IN_H * XP_STRIDE + IN_H * HS4_STRIDE + IN_H * HS1_STRIDE)

__global__ void __launch_bounds__(NTHREADS, 3)
ssim_kernel(const float* __restrict__ X, const float* __restrict__ Y,
            float* __restrict__ out)
{
    extern __shared__ float sm[];
    float* xp  = sm;                                 // x plane
    float* yp  = xp  + IN_H * XP_STRIDE;             // y plane
    float* hs4 = yp  + IN_H * XP_STRIDE;             // 4 fields interleaved
    float* hs1 = hs4 + IN_H * HS4_STRIDE;            // xy-blur plane

    const uint32_t xp_s = (uint32_t)__cvta_generic_to_shared(xp);
    const uint32_t yp_s = (uint32_t)__cvta_generic_to_shared(yp);

    const int tid = threadIdx.x;
    const int c0  = blockIdx.x * TILE_W;
    const int r0  = blockIdx.y * TILE_H;
    const int n   = blockIdx.z;

    const int s2c  = tid & 31;    // stage-2 column
    const int s2rg = tid >> 5;    // stage-2 row group (8 rows)

    // 6 broadcast weight pairs (symmetric kernel), hoisted into registers
    uint64_t ww[6];
#pragma unroll
    for (int t = 0; t < 6; t++) ww[t] = bcast2(gw(t));

    // ---- channel-invariant load addressing, computed ONCE ----
    int      goff[4];   // global element offset (per-channel base added later)
    uint32_t soff[4];   // smem byte offset
#pragma unroll
    for (int s = 0; s < 4; s++) {
        int i = tid + s * NTHREADS;
        if (i >= NCHUNK) i = NCHUNK - 1;     // slot 3 masked at issue time
        int r = i / 11;
        int f = i - r * 11;
        int gr = r0 + r;     if (gr > IMG_H - 1) gr = IMG_H - 1;  // clamp: OOB
        int gc = c0 + 4 * f; if (gc > IMG_W - 4) gc = IMG_W - 4;  // cells unused
        goff[s] = gr * IMG_W + gc;
        soff[s] = (uint32_t)(r * XP_STRIDE + 4 * f) * 4u;
    }
    const bool slot3 = (tid < NCHUNK - 3 * NTHREADS);   // tid < 46

    auto load_async = [&](int ch) {
        const float* Xb = X + (size_t)(n * NCH + ch) * (IMG_W * IMG_H);
        const float* Yb = Y + (size_t)(n * NCH + ch) * (IMG_W * IMG_H);
#pragma unroll
        for (int s = 0; s < 3; s++) {
            cp_async16(xp_s + soff[s], Xb + goff[s]);
            cp_async16(yp_s + soff[s], Yb + goff[s]);
        }
        if (slot3) {
            cp_async16(xp_s + soff[3], Xb + goff[3]);
            cp_async16(yp_s + soff[3], Yb + goff[3]);
        }
        cp_commit();
    };

    // stage-2 pointers (channel-invariant)
    const float* h4r = hs4 + (s2rg * 8) * HS4_STRIDE + 4 * s2c;
    const float* h1r = hs1 + (s2rg * 8) * HS1_STRIDE + s2c;

    float sacc[8];
#pragma unroll
    for (int j = 0; j < 8; j++) sacc[j] = 0.0f;

    // prologue: fetch channel 0
    load_async(0);
    cp_wait0();
    __syncthreads();

    for (int ch = 0; ch < NCH; ++ch) {
        // ---- stage 1: horizontal blur of 5 fields (f32x2-packed) ----
        for (int task = tid; task < IN_H * 4; task += NTHREADS) {
            int g  = task / IN_H;
            int r  = task - g * IN_H;
            int g8 = g * 8;

            uint64_t a01[8], a23[8];
            float a4[8];

            const float* xr = xp + r * XP_STRIDE + g8;
            const float* yr = yp + r * XP_STRIDE + g8;
            float4 xq, yq;
#pragma unroll
            for (int k = 0; k < 18; k++) {
                if ((k & 3) == 0) {   // g8+k+4 <= 44: in-row (stride 44)
                    xq = *reinterpret_cast<const float4*>(xr + k);
                    yq = *reinterpret_cast<const float4*>(yr + k);
                }
                float x = ((k & 3) == 0) ? xq.x : ((k & 3) == 1) ? xq.y
                        : ((k & 3) == 2) ? xq.z : xq.w;
                float y = ((k & 3) == 0) ? yq.x : ((k & 3) == 1) ? yq.y
                        : ((k & 3) == 2) ? yq.z : yq.w;
                uint64_t xyp = pk2(x, y);            // (x, y)
                uint64_t sqp = mul2(xyp, xyp);       // (x^2, y^2)
                float xy = x * y;
#pragma unroll
                for (int j = 0; j < 8; j++) {
                    const int t = k - j;
                    if (t == 0) {                    // first tap: init (no MOV 0)
                        a01[j] = mul2(xyp, ww[0]);
                        a23[j] = mul2(sqp, ww[0]);
                        a4[j]  = xy * gw(0);
                    } else if (t > 0 && t < 11) {
                        const int tm = (t < 6) ? t : 10 - t;
                        fma2(a01[j], xyp, ww[tm]);   // blur(x), blur(y)
                        fma2(a23[j], sqp, ww[tm]);   // blur(x2), blur(y2)
                        a4[j] = fmaf(xy, gw(t), a4[j]);
                    }
                }
            }
            float* h4 = hs4 + r * HS4_STRIDE + 4 * g8;
            float* h1 = hs1 + r * HS1_STRIDE + g8;
#pragma unroll
            for (int j = 0; j < 8; j++) {
                *reinterpret_cast<uint64_t*>(h4 + 4 * j)     = a01[j];
                *reinterpret_cast<uint64_t*>(h4 + 4 * j + 2) = a23[j];
                h1[j] = a4[j];   // scalar: hs1 stride is odd (alignment!)
            }
        }
        __syncthreads();   // xs reads + hs writes done

        // ---- prefetch next channel while stage 2 computes ----
        if (ch + 1 < NCH) load_async(ch + 1);

        // ---- stage 2: vertical blur (f32x2-packed) + SSIM map ----
        {
            uint64_t b01[8], b23[8];
            float b4[8];
#pragma unroll
            for (int k = 0; k < 18; k++) {
                ulonglong2 v = *reinterpret_cast<const ulonglong2*>(h4r + k * HS4_STRIDE);
                float v4 = h1r[k * HS1_STRIDE];
#pragma unroll
                for (int j = 0; j < 8; j++) {
                    const int t = k - j;
                    if (t == 0) {                    // first tap: init
                        b01[j] = mul2(v.x, ww[0]);
                        b23[j] = mul2(v.y, ww[0]);
                        b4[j]  = v4 * gw(0);
                    } else if (t > 0 && t < 11) {
                        const int tm = (t < 6) ? t : 10 - t;
                        fma2(b01[j], v.x, ww[tm]);   // mu1, mu2
                        fma2(b23[j], v.y, ww[tm]);   // blur(x2), blur(y2)
                        b4[j] = fmaf(v4, gw(t), b4[j]);
                    }
                }
            }
#pragma unroll
            for (int j = 0; j < 8; j++) {
                float2 mu  = unpk(b01[j]);               // mu1, mu2
                uint64_t msqp = mul2(b01[j], b01[j]);    // mu1^2, mu2^2
                float2 msq = unpk(msqp);
                float2 sg  = unpk(b23[j]);               // blur(x2), blur(y2)
                float m12 = mu.x * mu.y;
                float s1  = sg.x - msq.x;
                float s2v = sg.y - msq.y;
                float s12 = b4[j] - m12;
                float num = (2.0f * s12 + C2v) * (2.0f * m12 + C1v);
                float den = (s1 + s2v + C2v) * (msq.x + msq.y + C1v);
                sacc[j] += __fdividef(num, den);
            }
        }

        if (ch + 1 < NCH) cp_wait0();
        __syncthreads();   // hs reads done + next xs tiles visible
    }

    // ---- write: 1 - mean over channels ----
#pragma unroll
    for (int j = 0; j < 8; j++) {
        int oh = r0 + s2rg * 8 + j;
        int ow = c0 + s2c;
        if (oh < OUT_H && ow < OUT_W) {
            out[((size_t)n * OUT_H + oh) * OUT_W + ow] =
                1.0f - sacc[j] * (1.0f / 3.0f);
        }
    }
}

extern "C" void kernel_launch(void* const* d_in, const int* in_sizes, int n_in,
                              void* d_out, int out_size)
{
    const float* X = (const float*)d_in[0];
    const float* Y = (const float*)d_in[1];
    float* out = (float*)d_out;

    const int smem_bytes = SMEM_FLOATS * (int)sizeof(float);  // 74888
    cudaFuncSetAttribute(ssim_kernel,
                         cudaFuncAttributeMaxDynamicSharedMemorySize,
                         smem_bytes);

    dim3 grid((OUT_W + TILE_W - 1) / TILE_W,   // 16
              (OUT_H + TILE_H - 1) / TILE_H,   // 8
              16);                             // batch
    ssim_kernel<<<grid, NTHREADS, smem_bytes>>>(X, Y, out);
}

// round 15
// speedup vs baseline: 1.0304x; 1.0304x over previous
#include <cuda_runtime.h>
#include <cstddef>
#include <cstdint>

// ---------------- compile-time Gaussian weights (win=11, sigma=1.5) ----------
__host__ __device__ __forceinline__ constexpr float gw(int t) {
    return (t == 0  || t == 10) ? 0.00102848f
         : (t == 1  || t == 9 ) ? 0.00759876f
         : (t == 2  || t == 8 ) ? 0.03600078f
         : (t == 3  || t == 7 ) ? 0.10936057f
         : (t == 4  || t == 6 ) ? 0.21300557f
         :                        0.26601165f;   // t == 5
}

// ---------------- packed f32x2 helpers (sm_100+) ----------------
__device__ __forceinline__ uint64_t bcast2(float w) {
    uint64_t r; asm("mov.b64 %0, {%1, %1};" : "=l"(r) : "f"(w)); return r;
}
__device__ __forceinline__ uint64_t pk2(float x, float y) {
    uint64_t r; asm("mov.b64 %0, {%1, %2};" : "=l"(r) : "f"(x), "f"(y)); return r;
}
__device__ __forceinline__ float2 unpk(uint64_t v) {
    float2 p; asm("mov.b64 {%0, %1}, %2;" : "=f"(p.x), "=f"(p.y) : "l"(v)); return p;
}
__device__ __forceinline__ void fma2(uint64_t& d, uint64_t a, uint64_t b) {
    asm("fma.rn.f32x2 %0, %1, %2, %0;" : "+l"(d) : "l"(a), "l"(b));
}
__device__ __forceinline__ uint64_t mul2(uint64_t a, uint64_t b) {
    uint64_t d; asm("mul.rn.f32x2 %0, %1, %2;" : "=l"(d) : "l"(a), "l"(b)); return d;
}

// ---------------- cp.async helpers ----------------
__device__ __forceinline__ void cp_async16(uint32_t dst_smem, const void* src) {
    asm volatile("cp.async.cg.shared.global [%0], [%1], 16;"
                 :: "r"(dst_smem), "l"(src));
}
__device__ __forceinline__ void cp_commit() {
    asm volatile("cp.async.commit_group;" ::: "memory");
}
__device__ __forceinline__ void cp_wait0() {
    asm volatile("cp.async.wait_group 0;" ::: "memory");
}

#define TILE_W 32
#define TILE_H 72
#define IN_W   42          // TILE_W + 10
#define IN_H   82          // TILE_H + 10
#define NTHREADS 384       // 12 warps, 2 blocks/SM -> 24 warps/SM

#define IMG_W 512
#define IMG_H 512
#define OUT_W 502
#define OUT_H 502
#define NCH   3

#define XP_STRIDE 44       // x/y planes: 16B-aligned rows, 12r mod 32 -> CF .128
#define HS4_STRIDE 132     // 4 fields interleaved (float4 per col), 16B-aligned rows
#define HS1_STRIDE 33      // xy-blur scalar plane, odd stride (scalar access only!)

#define NCHUNK (IN_H * 11) // 902 cp.async 16B chunks per plane per channel
#define S1_TASKS (IN_H * 4)  // 328 <= 384: single non-divergent round
#define S2_ROWS 6            // 12 groups x 6 rows = 72 = TILE_H

static constexpr float C1v = 6.5025f;    // (0.01*255)^2
static constexpr float C2v = 58.5225f;   // (0.03*255)^2

// smem floats: 2*82*44 + 82*132 + 82*33 = 20746 -> 82984 B -> 2 blocks/SM
#define SMEM_FLOATS (2 * IN_H * XP_STRIDE + IN_H * HS4_STRIDE + IN_H * HS1_STRIDE)

__global__ void __launch_bounds__(NTHREADS, 2)
ssim_kernel(const float* __restrict__ X, const float* __restrict__ Y,
            float* __restrict__ out)
{
    extern __shared__ float sm[];
    float* xp  = sm;                                 // x plane
    float* yp  = xp  + IN_H * XP_STRIDE;             // y plane
    float* hs4 = yp  + IN_H * XP_STRIDE;             // 4 fields interleaved
    float* hs1 = hs4 + IN_H * HS4_STRIDE;            // xy-blur plane

    const uint32_t xp_s = (uint32_t)__cvta_generic_to_shared(xp);
    const uint32_t yp_s = (uint32_t)__cvta_generic_to_shared(yp);

    const int tid = threadIdx.x;
    const int c0  = blockIdx.x * TILE_W;
    const int r0  = blockIdx.y * TILE_H;
    const int n   = blockIdx.z;

    const int s2c  = tid & 31;    // stage-2 column
    const int s2rg = tid >> 5;    // stage-2 row group (6 rows each, 12 groups)

    // 6 broadcast weight pairs (symmetric kernel), hoisted into registers
    uint64_t ww[6];
#pragma unroll
    for (int t = 0; t < 6; t++) ww[t] = bcast2(gw(t));

    float sacc[S2_ROWS];
#pragma unroll
    for (int j = 0; j < S2_ROWS; j++) sacc[j] = 0.0f;

    // async tile loader: channel ch -> xp/yp planes. OOB clamped (those
    // tile cells only feed outputs that are discarded by the write guard).
    auto load_async = [&](int ch) {
        const float* Xb = X + (size_t)(n * NCH + ch) * (IMG_W * IMG_H);
        const float* Yb = Y + (size_t)(n * NCH + ch) * (IMG_W * IMG_H);
        for (int i = tid; i < NCHUNK; i += NTHREADS) {
            int r = i / 11;
            int f = i - r * 11;
            int gr = r0 + r;     if (gr > IMG_H - 1) gr = IMG_H - 1;
            int gc = c0 + 4 * f; if (gc > IMG_W - 4) gc = IMG_W - 4;
            size_t o = (size_t)gr * IMG_W + gc;
            uint32_t doff = (uint32_t)(r * XP_STRIDE + 4 * f) * 4u;
            cp_async16(xp_s + doff, Xb + o);
            cp_async16(yp_s + doff, Yb + o);
        }
        cp_commit();
    };

    // prologue: fetch channel 0
    load_async(0);
    cp_wait0();
    __syncthreads();

    for (int ch = 0; ch < NCH; ++ch) {
        // ---- stage 1: horizontal blur of 5 fields (f32x2-packed) ----
        // 82 rows x 4 col-groups = 328 tasks, one round, no remainder.
        if (tid < S1_TASKS) {
            int g  = tid / IN_H;
            int r  = tid - g * IN_H;
            int g8 = g * 8;

            uint64_t a01[8], a23[8];
            float a4[8];
#pragma unroll
            for (int j = 0; j < 8; j++) { a01[j] = 0ull; a23[j] = 0ull; a4[j] = 0.0f; }

            const float* xr = xp + r * XP_STRIDE + g8;
            const float* yr = yp + r * XP_STRIDE + g8;
            float4 xq, yq; float2 xt, yt;
#pragma unroll
            for (int k = 0; k < 18; k++) {
                if ((k & 3) == 0) {
                    if (k < 16) {
                        xq = *reinterpret_cast<const float4*>(xr + k);
                        yq = *reinterpret_cast<const float4*>(yr + k);
                    } else {
                        xt = *reinterpret_cast<const float2*>(xr + k);
                        yt = *reinterpret_cast<const float2*>(yr + k);
                    }
                }
                float x, y;
                if (k < 16) {
                    x = ((k & 3) == 0) ? xq.x : ((k & 3) == 1) ? xq.y
                      : ((k & 3) == 2) ? xq.z : xq.w;
                    y = ((k & 3) == 0) ? yq.x : ((k & 3) == 1) ? yq.y
                      : ((k & 3) == 2) ? yq.z : yq.w;
                } else {
                    x = ((k & 1) == 0) ? xt.x : xt.y;
                    y = ((k & 1) == 0) ? yt.x : yt.y;
                }
                uint64_t xyp = pk2(x, y);            // (x, y)
                uint64_t sqp = mul2(xyp, xyp);       // (x^2, y^2)
                float xy = x * y;
#pragma unroll
                for (int j = 0; j < 8; j++) {
                    const int t = k - j;
                    if (t >= 0 && t < 11) {
                        const int tm = (t < 6) ? t : 10 - t;
                        fma2(a01[j], xyp, ww[tm]);   // blur(x), blur(y)
                        fma2(a23[j], sqp, ww[tm]);   // blur(x2), blur(y2)
                        a4[j] = fmaf(xy, gw(t), a4[j]);  // blur(xy), FFMA-imm
                    }
                }
            }
            float* h4 = hs4 + r * HS4_STRIDE + 4 * g8;
            float* h1 = hs1 + r * HS1_STRIDE + g8;
#pragma unroll
            for (int j = 0; j < 8; j++) {
                *reinterpret_cast<uint64_t*>(h4 + 4 * j)     = a01[j];
                *reinterpret_cast<uint64_t*>(h4 + 4 * j + 2) = a23[j];
                h1[j] = a4[j];   // scalar: hs1 stride is odd (alignment!)
            }
        }
        __syncthreads();   // xs reads + hs writes done

        // ---- prefetch next channel while stage 2 computes ----
        if (ch + 1 < NCH) load_async(ch + 1);

        // ---- stage 2: vertical blur (f32x2-packed) + SSIM map, 6 rows ----
        {
            uint64_t b01[S2_ROWS], b23[S2_ROWS];
            float b4[S2_ROWS];
#pragma unroll
            for (int j = 0; j < S2_ROWS; j++) { b01[j] = 0ull; b23[j] = 0ull; b4[j] = 0.0f; }

            const float* h4 = hs4 + (s2rg * S2_ROWS) * HS4_STRIDE + 4 * s2c;
            const float* h1 = hs1 + (s2rg * S2_ROWS) * HS1_STRIDE + s2c;
#pragma unroll
            for (int k = 0; k < S2_ROWS + 10; k++) {   // 16 rows
                ulonglong2 v = *reinterpret_cast<const ulonglong2*>(h4 + k * HS4_STRIDE);
                float v4 = h1[k * HS1_STRIDE];
#pragma unroll
                for (int j = 0; j < S2_ROWS; j++) {
                    const int t = k - j;
                    if (t >= 0 && t < 11) {
                        const int tm = (t < 6) ? t : 10 - t;
                        fma2(b01[j], v.x, ww[tm]);   // mu1, mu2
                        fma2(b23[j], v.y, ww[tm]);   // blur(x2), blur(y2)
                        b4[j] = fmaf(v4, gw(t), b4[j]);
                    }
                }
            }
#pragma unroll
            for (int j = 0; j < S2_ROWS; j++) {
                float2 mu  = unpk(b01[j]);               // mu1, mu2
                uint64_t msqp = mul2(b01[j], b01[j]);    // mu1^2, mu2^2
                float2 msq = unpk(msqp);
                float2 sg  = unpk(b23[j]);               // blur(x2), blur(y2)
                float m12 = mu.x * mu.y;
                float s1  = sg.x - msq.x;
                float s2v = sg.y - msq.y;
                float s12 = b4[j] - m12;
                float num = (2.0f * s12 + C2v) * (2.0f * m12 + C1v);
                float den = (s1 + s2v + C2v) * (msq.x + msq.y + C1v);
                sacc[j] += __fdividef(num, den);
            }
        }

        if (ch + 1 < NCH) cp_wait0();
        __syncthreads();   // hs reads done + next xs tiles visible
    }

    // ---- write: 1 - mean over channels ----
#pragma unroll
    for (int j = 0; j < S2_ROWS; j++) {
        int oh = r0 + s2rg * S2_ROWS + j;
        int ow = c0 + s2c;
        if (oh < OUT_H && ow < OUT_W) {
            out[((size_t)n * OUT_H + oh) * OUT_W + ow] =
                1.0f - sacc[j] * (1.0f / 3.0f);
        }
    }
}

extern "C" void kernel_launch(void* const* d_in, const int* in_sizes, int n_in,
                              void* d_out, int out_size)
{
    const float* X = (const float*)d_in[0];
    const float* Y = (const float*)d_in[1];
    float* out = (float*)d_out;

    const int smem_bytes = SMEM_FLOATS * (int)sizeof(float);  // 82984
    cudaFuncSetAttribute(ssim_kernel,
                         cudaFuncAttributeMaxDynamicSharedMemorySize,
                         smem_bytes);

    dim3 grid((OUT_W + TILE_W - 1) / TILE_W,   // 16
              (OUT_H + TILE_H - 1) / TILE_H,   // 7
              16);                             // batch
    ssim_kernel<<<grid, NTHREADS, smem_bytes>>>(X, Y, out);
}